// round 17
// baseline (speedup 1.0000x reference)
#include <cuda_runtime.h>
#include <cuda_fp16.h>
#include <cstdint>
#include <math.h>

// ---------------------------------------------------------------------------
// Problem constants
// ---------------------------------------------------------------------------
namespace {
constexpr int NTOK = 8192;      // B*T
constexpr int CD   = 1024;      // C
constexpr int NE   = 8;
constexpr int HD   = 1408;
constexpr int HSD  = 2816;
constexpr int NPAIR = NTOK * 2;

// GEMM tiling: fp16 m16n8k16, BM=256, BN=128, BK=32, 3-stage, 512 threads
constexpr int BM = 256, BN = 128, BK = 32, NTHR = 512, S = 3;
constexpr int SPAD = 8;                          // halves of row padding
constexpr int SSTR = BK + SPAD;                  // 40 halves (80 B row stride)
constexpr int ASTG_B = BM * SSTR * 2;            // 20480 B per A stage
constexpr int BSTG_B = BN * SSTR * 2;            // 10240 B per B stage
constexpr int A_REGION = S * ASTG_B;             // 61440
constexpr unsigned SMEM_DYN = S * (ASTG_B + BSTG_B);  // 92160 B
}

// ---------------------------------------------------------------------------
// Scratch (allocation-free __device__ globals; referenced ONLY in device code)
// ---------------------------------------------------------------------------
__device__ int    g_counts[NE];
__device__ int    g_offsets[NE];
__device__ int    g_cursor[NE];
__device__ int    g_tok[NPAIR];
__device__ float  g_gatew[NPAIR];
__device__ int    g_dest[NPAIR];
__device__ int    g_topi[NPAIR];
__device__ float  g_topp[NPAIR];

__device__ __half g_xh  [(size_t)NTOK * CD];          // half x
__device__ __half g_w12i[(size_t)NE * (2*HD) * CD];   // [e][2c+{0,1}][k] interleaved W1/W2, transposed
__device__ __half g_ws12[(size_t)(2*HSD) * CD];       // interleaved Ws1/Ws2, transposed
__device__ __half g_w3t [(size_t)NE * CD * HD];       // W3 transposed [n][k]
__device__ __half g_ws3t[(size_t)CD * HSD];           // Ws3 transposed
__device__ __half g_hh  [(size_t)NPAIR * HD];         // gated expert hidden (half)
__device__ __half g_hsh [(size_t)NTOK * HSD];         // gated shared hidden (half)
__device__ float  g_yp  [(size_t)NPAIR * CD];         // per-pair expert outputs (fp32)

// ---------------------------------------------------------------------------
// Helpers
// ---------------------------------------------------------------------------
__device__ __forceinline__ float silu_mul(float g, float u) {
    return (g / (1.0f + expf(-g))) * u;
}
__device__ __forceinline__ void mma16(float d[4], const uint32_t a[4],
                                      uint32_t b0, uint32_t b1) {
    asm volatile(
        "mma.sync.aligned.m16n8k16.row.col.f32.f16.f16.f32 "
        "{%0,%1,%2,%3},{%4,%5,%6,%7},{%8,%9},{%0,%1,%2,%3};"
        : "+f"(d[0]), "+f"(d[1]), "+f"(d[2]), "+f"(d[3])
        : "r"(a[0]), "r"(a[1]), "r"(a[2]), "r"(a[3]), "r"(b0), "r"(b1));
}
__device__ __forceinline__ void cpa16(uint32_t smem_dst, const __half* gsrc) {
    asm volatile("cp.async.cg.shared.global [%0], [%1], 16;" :: "r"(smem_dst), "l"(gsrc));
}
__device__ __forceinline__ void ldm4(uint32_t& r0, uint32_t& r1,
                                     uint32_t& r2, uint32_t& r3, uint32_t addr) {
    asm volatile("ldmatrix.sync.aligned.m8n8.x4.shared.b16 {%0,%1,%2,%3}, [%4];"
                 : "=r"(r0), "=r"(r1), "=r"(r2), "=r"(r3) : "r"(addr));
}

// ---------------------------------------------------------------------------
// Router / routing bookkeeping (proven code)
// ---------------------------------------------------------------------------
__global__ void router_kernel(const float* __restrict__ x,
                              const float* __restrict__ Wg) {
    int warp = threadIdx.x >> 5, lane = threadIdx.x & 31;
    int t = blockIdx.x * 8 + warp;
    const float* xr = x + (size_t)t * CD;
    float acc[NE];
#pragma unroll
    for (int e = 0; e < NE; e++) acc[e] = 0.f;
    for (int c = lane; c < CD; c += 32) {
        float xv = __ldg(xr + c);
        const float4* wr = reinterpret_cast<const float4*>(Wg + c * NE);
        float4 w0 = wr[0], w1 = wr[1];
        acc[0] += xv * w0.x; acc[1] += xv * w0.y;
        acc[2] += xv * w0.z; acc[3] += xv * w0.w;
        acc[4] += xv * w1.x; acc[5] += xv * w1.y;
        acc[6] += xv * w1.z; acc[7] += xv * w1.w;
    }
#pragma unroll
    for (int off = 16; off > 0; off >>= 1)
#pragma unroll
        for (int e = 0; e < NE; e++)
            acc[e] += __shfl_xor_sync(0xffffffffu, acc[e], off);

    if (lane == 0) {
        int i0 = 0; float l0 = acc[0];
#pragma unroll
        for (int e = 1; e < NE; e++) if (acc[e] > l0) { l0 = acc[e]; i0 = e; }
        int i1 = (i0 == 0) ? 1 : 0; float l1 = acc[i1];
#pragma unroll
        for (int e = 0; e < NE; e++)
            if (e != i0 && acc[e] > l1) { l1 = acc[e]; i1 = e; }
        float ex = expf(l1 - l0);
        float inv = 1.0f / (1.0f + ex);
        g_topi[2*t]   = i0;  g_topi[2*t+1] = i1;
        g_topp[2*t]   = inv; g_topp[2*t+1] = ex * inv;
        atomicAdd(&g_counts[i0], 1);
        atomicAdd(&g_counts[i1], 1);
    }
}

__global__ void zero_kernel() {
    if (threadIdx.x < NE) g_counts[threadIdx.x] = 0;
}
__global__ void offsets_kernel() {
    if (threadIdx.x == 0) {
        int s = 0;
        for (int e = 0; e < NE; e++) { g_offsets[e] = s; g_cursor[e] = s; s += g_counts[e]; }
    }
}
__global__ void scatter_kernel() {
    int t = blockIdx.x * blockDim.x + threadIdx.x;
    if (t < NTOK) {
#pragma unroll
        for (int k = 0; k < 2; k++) {
            int e = g_topi[2*t + k];
            int pos = atomicAdd(&g_cursor[e], 1);
            g_tok[pos]   = t;
            g_gatew[pos] = g_topp[2*t + k];
            g_dest[pos]  = 2*t + k;
        }
    }
}

// ---------------------------------------------------------------------------
// x -> half
// ---------------------------------------------------------------------------
__global__ void halfx_kernel(const float* __restrict__ x) {
    size_t i = (size_t)blockIdx.x * blockDim.x + threadIdx.x;
    float4 v = reinterpret_cast<const float4*>(x)[i];
    __half2* d = reinterpret_cast<__half2*>(g_xh) + i * 2;
    d[0] = __floats2half2_rn(v.x, v.y);
    d[1] = __floats2half2_rn(v.z, v.w);
}

// ---------------------------------------------------------------------------
// Transpose + convert: src [z][R][C] fp32 -> dst rows oc = c*OS+OO, dst[z][oc][R] half
// DSTID: 0 g_w12i, 1 g_ws12, 2 g_w3t, 3 g_ws3t
// ---------------------------------------------------------------------------
template<int DSTID, int OS, int OO>
__global__ void transpose_half_kernel(const float* __restrict__ src,
                                      int R, int C,
                                      size_t in_bstride, size_t out_bstride) {
    __shared__ float t[32][33];
    __half* dstb = (DSTID == 0) ? g_w12i
                 : (DSTID == 1) ? g_ws12
                 : (DSTID == 2) ? g_w3t
                                : g_ws3t;
    const float* ip = src + (size_t)blockIdx.z * in_bstride;
    __half* op = dstb + (size_t)blockIdx.z * out_bstride;
    int c0 = blockIdx.x * 32, r0 = blockIdx.y * 32;
    int tx = threadIdx.x, ty = threadIdx.y;
#pragma unroll
    for (int j = 0; j < 4; j++)
        t[ty + 8*j][tx] = ip[(size_t)(r0 + ty + 8*j) * C + c0 + tx];
    __syncthreads();
#pragma unroll
    for (int j = 0; j < 4; j++) {
        int oc = (c0 + ty + 8*j) * OS + OO;
        op[(size_t)oc * R + r0 + tx] = __float2half_rn(t[tx][ty + 8*j]);
    }
}

// ---------------------------------------------------------------------------
// GEMM core shared by both stages.
// blockIdx.z in [0, NE]: z < NE -> expert z; z == NE -> shared expert.
// STAGE1: A[CD] (x, gathered for experts), B interleaved W12 -> silu -> hidden(half)
// STAGE2: A[KDIM runtime] (hidden), B W3 -> g_yp (scaled) or Out
// 512 threads, 16 warps (8m x 2n), warptile 32x64, 3-stage cp.async ring.
// ---------------------------------------------------------------------------
template<int STAGE>
__global__ __launch_bounds__(NTHR)
void gemm_moe(float* __restrict__ Out) {
    extern __shared__ __align__(16) char dsm[];
    const uint32_t sbase = (uint32_t)__cvta_generic_to_shared(dsm);

    const int z = blockIdx.z;
    const bool expert = (z < NE);
    const int e   = expert ? z : 0;
    const int M   = expert ? g_counts[e]  : NTOK;
    const int off = expert ? g_offsets[e] : 0;
    const int m0  = blockIdx.y * BM;
    if (m0 >= M) return;

    // per-branch geometry
    int kd, nrows;
    const __half *Abase, *Bbase;
    if (STAGE == 1) {
        kd = CD;
        nrows = expert ? 2*HD : 2*HSD;
        Abase = g_xh;
        Bbase = expert ? (g_w12i + (size_t)e * (2*HD) * CD) : g_ws12;
    } else {
        kd    = expert ? HD : HSD;
        nrows = CD;
        Abase = expert ? g_hh : g_hsh;
        Bbase = expert ? (g_w3t + (size_t)e * CD * HD) : g_ws3t;
    }
    const int n0 = blockIdx.x * BN;
    if (n0 >= nrows) return;

    const int tid = threadIdx.x;

    // ---- loaders: A 1024 chunks -> 2/thread; B 512 chunks -> 1/thread
    const __half* ap[2]; uint32_t adst[2];
#pragma unroll
    for (int j = 0; j < 2; j++) {
        int chunk = tid + j * NTHR;
        int arow = chunk >> 2;
        int ac8  = (chunk & 3) * 8;
        int rr = m0 + arow; if (rr >= M) rr = M - 1;
        int row;
        if (STAGE == 1) row = expert ? g_tok[off + rr] : rr;
        else            row = expert ? (off + rr) : rr;
        ap[j] = Abase + (size_t)row * kd + ac8;
        adst[j] = sbase + (uint32_t)(arow * SSTR + ac8) * 2;
    }
    const int brow = tid >> 2, bc8 = (tid & 3) * 8;
    const __half* bp = Bbase + (size_t)(n0 + brow) * kd + bc8;
    const uint32_t bdst = sbase + A_REGION + (uint32_t)(brow * SSTR + bc8) * 2;

    auto load_stage = [&](int kt, int buf) {
        int k0 = kt * BK;
#pragma unroll
        for (int j = 0; j < 2; j++)
            cpa16(adst[j] + buf * ASTG_B, ap[j] + k0);
        cpa16(bdst + buf * BSTG_B, bp + k0);
        asm volatile("cp.async.commit_group;");
    };

    // ---- fragment mapping: 16 warps = 8m x 2n, warptile 32x64
    const int wid = tid >> 5, wm = wid & 7, wn = wid >> 3;
    const int lane = tid & 31, grp = lane >> 2, tig = lane & 3;
    float acc[2][8][4] = {};

    const uint32_t aAddr = sbase
        + (uint32_t)((wm * 32 + (lane & 15)) * SSTR) * 2
        + (uint32_t)(lane >> 4) * 16;
    const uint32_t bAddr = sbase + A_REGION
        + (uint32_t)((wn * 64 + (lane & 7) + ((lane >> 4) << 3)) * SSTR) * 2
        + (uint32_t)((lane >> 3) & 1) * 16;

    auto compute_stage = [&](int buf) {
        uint32_t ab = aAddr + buf * ASTG_B;
        uint32_t bb = bAddr + buf * BSTG_B;
#pragma unroll
        for (int ks = 0; ks < 2; ks++) {
            uint32_t koff = ks * 32;
            uint32_t a[2][4];
            ldm4(a[0][0], a[0][1], a[0][2], a[0][3], ab + koff);
            ldm4(a[1][0], a[1][1], a[1][2], a[1][3], ab + 16 * SSTR * 2 + koff);
            uint32_t b[8][2];
#pragma unroll
            for (int np = 0; np < 4; np++)
                ldm4(b[2*np][0], b[2*np][1], b[2*np+1][0], b[2*np+1][1],
                     bb + np * 16 * SSTR * 2 + koff);
#pragma unroll
            for (int nt = 0; nt < 8; nt++) {
                mma16(acc[0][nt], a[0], b[nt][0], b[nt][1]);
                mma16(acc[1][nt], a[1], b[nt][0], b[nt][1]);
            }
        }
    };

    // ---- 3-stage pipeline, one barrier per K-iteration
    const int KT = kd / BK;
    load_stage(0, 0);
    load_stage(1, 1);
#pragma unroll 1
    for (int kt = 0; kt < KT; ++kt) {
        if (kt + 2 < KT) {
            asm volatile("cp.async.wait_group 1;");
        } else {
            asm volatile("cp.async.wait_group 0;");
        }
        __syncthreads();
        if (kt + 2 < KT) load_stage(kt + 2, (kt + 2) % S);
        compute_stage(kt % S);
        __syncthreads();
    }

    // ---- epilogue
#pragma unroll
    for (int mt = 0; mt < 2; mt++) {
        int rb = wm * 32 + mt * 16 + grp;
#pragma unroll
        for (int half_ = 0; half_ < 2; half_++) {
            int r = m0 + rb + half_ * 8;
            if (r < M) {
                if (STAGE == 1) {
                    __half* dst = expert ? (g_hh + (size_t)(off + r) * HD)
                                         : (g_hsh + (size_t)r * HSD);
                    int hbase = n0 / 2;
#pragma unroll
                    for (int nt = 0; nt < 8; nt++) {
                        int hcol = hbase + wn * 32 + nt * 4 + tig;
                        float gate = acc[mt][nt][half_*2+0];
                        float up   = acc[mt][nt][half_*2+1];
                        dst[hcol] = __float2half_rn(silu_mul(gate, up));
                    }
                } else {
                    float scale = 1.0f; float* dst;
                    if (expert) {
                        scale = g_gatew[off + r];
                        dst   = g_yp + (size_t)g_dest[off + r] * CD + n0;
                    } else {
                        dst   = Out + (size_t)r * CD + n0;
                    }
#pragma unroll
                    for (int nt = 0; nt < 8; nt++) {
                        int col = wn * 64 + nt * 8 + tig * 2;
                        float v0 = acc[mt][nt][half_*2+0] * scale;
                        float v1 = acc[mt][nt][half_*2+1] * scale;
                        *reinterpret_cast<float2*>(&dst[col]) = make_float2(v0, v1);
                    }
                }
            }
        }
    }
}

// ---------------------------------------------------------------------------
// Final combine: out[t] += yp[2t] + yp[2t+1]
// ---------------------------------------------------------------------------
__global__ void combine_kernel(float* __restrict__ Out) {
    size_t i = (size_t)blockIdx.x * blockDim.x + threadIdx.x;
    size_t t  = i / (CD / 4);
    size_t c4 = i % (CD / 4);
    float4* o = reinterpret_cast<float4*>(Out) + t * (CD / 4) + c4;
    const float4* p0 = reinterpret_cast<const float4*>(g_yp) + (2 * t) * (CD / 4) + c4;
    const float4* p1 = p0 + (CD / 4);
    float4 a = *o, x0 = *p0, x1 = *p1;
    a.x += x0.x + x1.x; a.y += x0.y + x1.y;
    a.z += x0.z + x1.z; a.w += x0.w + x1.w;
    *o = a;
}

// ---------------------------------------------------------------------------
// Launch — only harness pointers cross the host/device boundary.
// ---------------------------------------------------------------------------
extern "C" void kernel_launch(void* const* d_in, const int* in_sizes, int n_in,
                              void* d_out, int out_size) {
    const float* x   = (const float*)d_in[0];
    const float* Wg  = (const float*)d_in[1];
    const float* W1  = (const float*)d_in[2];
    const float* W2  = (const float*)d_in[3];
    const float* W3  = (const float*)d_in[4];
    const float* Ws1 = (const float*)d_in[5];
    const float* Ws2 = (const float*)d_in[6];
    const float* Ws3 = (const float*)d_in[7];
    float* out = (float*)d_out;

    cudaFuncSetAttribute(gemm_moe<1>, cudaFuncAttributeMaxDynamicSharedMemorySize, SMEM_DYN);
    cudaFuncSetAttribute(gemm_moe<2>, cudaFuncAttributeMaxDynamicSharedMemorySize, SMEM_DYN);

    // routing
    zero_kernel<<<1, 32>>>();
    router_kernel<<<NTOK / 8, 256>>>(x, Wg);
    offsets_kernel<<<1, 32>>>();
    scatter_kernel<<<NTOK / 256, 256>>>();

    // operand conversion
    halfx_kernel<<<(NTOK * CD / 4) / 256, 256>>>(x);

    dim3 tb(32, 8);
    transpose_half_kernel<0, 2, 0><<<dim3(HD / 32, CD / 32, NE), tb>>>(
        W1, CD, HD, (size_t)CD * HD, (size_t)(2*HD) * CD);
    transpose_half_kernel<0, 2, 1><<<dim3(HD / 32, CD / 32, NE), tb>>>(
        W2, CD, HD, (size_t)CD * HD, (size_t)(2*HD) * CD);
    transpose_half_kernel<1, 2, 0><<<dim3(HSD / 32, CD / 32, 1), tb>>>(
        Ws1, CD, HSD, 0, 0);
    transpose_half_kernel<1, 2, 1><<<dim3(HSD / 32, CD / 32, 1), tb>>>(
        Ws2, CD, HSD, 0, 0);
    transpose_half_kernel<2, 1, 0><<<dim3(CD / 32, HD / 32, NE), tb>>>(
        W3, HD, CD, (size_t)HD * CD, (size_t)CD * HD);
    transpose_half_kernel<3, 1, 0><<<dim3(CD / 32, HSD / 32, 1), tb>>>(
        Ws3, HSD, CD, 0, 0);

    // stage 1 (experts z=0..7, shared z=8), fused silu epilogue
    gemm_moe<1><<<dim3(2*HSD / BN, NTOK / BM, NE + 1), NTHR, SMEM_DYN>>>(out);
    // stage 2 (experts -> g_yp scaled, shared -> out)
    gemm_moe<2><<<dim3(CD / BN, NTOK / BM, NE + 1), NTHR, SMEM_DYN>>>(out);

    // combine
    combine_kernel<<<(NTOK * CD / 4) / 256, 256>>>(out);
}